// round 5
// baseline (speedup 1.0000x reference)
#include <cuda_runtime.h>
#include <cuda_bf16.h>

// Problem constants
#define HH 64
#define WW 64
#define CIN 256
#define COUT 256
#define BB 8
#define KKT 9
#define HWSZ 4096            // H*W
#define KTOT 2304            // 9*256

typedef unsigned long long ull;

// ---------------- scratch (device globals: no allocation allowed) ----------
__device__ float  g_xn[BB * HWSZ * CIN];     // x in NHWC (33.5 MB)
__device__ float  g_wT[KTOT * COUT];         // W^T [k][oc], k=tap*256+c
__device__ float  g_wom[KKT * 27 * CIN];     // fused off/mod weights [tap][oc][c]
__device__ short4 g_sxy[BB * KKT * HWSZ];    // clamped corner coords
__device__ float4 g_swt[BB * KKT * HWSZ];    // bilinear*mask*valid weights
// im2col A, tiled: [(bt*32+mchunk)*16+cc][16 k][128 m]  (302 MB)
__device__ float  g_A[(size_t)BB * KKT * CIN * HWSZ];

// ---------------- helpers ---------------------------------------------------
__device__ __forceinline__ ull fma2(ull a, ull b, ull c) {
    ull d;
    asm("fma.rn.f32x2 %0, %1, %2, %3;" : "=l"(d) : "l"(a), "l"(b), "l"(c));
    return d;
}
__device__ __forceinline__ float2 upk2(ull v) {
    float2 r;
    asm("mov.b64 {%0, %1}, %2;" : "=f"(r.x), "=f"(r.y) : "l"(v));
    return r;
}
__device__ __forceinline__ ull dup2(float v) {
    ull r;
    asm("mov.b64 %0, {%1, %1};" : "=l"(r) : "f"(v));
    return r;
}
__device__ __forceinline__ float sum2(ull v) {
    float2 r = upk2(v);
    return r.x + r.y;
}
__device__ __forceinline__ void cpa16(unsigned int s, const void* g) {
    asm volatile("cp.async.cg.shared.global [%0], [%1], 16;" :: "r"(s), "l"(g));
}

// ---------------- kernel: NCHW -> NHWC transpose of x ----------------------
__global__ void k_transpose(const float* __restrict__ x) {
    __shared__ float tile[32][33];
    int b  = blockIdx.z;
    int p0 = blockIdx.x * 32;
    int c0 = blockIdx.y * 32;
    const float* xb = x    + (size_t)b * (CIN * HWSZ);
    float*       ob = g_xn + (size_t)b * (HWSZ * CIN);
    int tx = threadIdx.x, ty = threadIdx.y;
#pragma unroll
    for (int i = 0; i < 4; i++)
        tile[ty + i * 8][tx] = xb[(size_t)(c0 + ty + i * 8) * HWSZ + p0 + tx];
    __syncthreads();
#pragma unroll
    for (int i = 0; i < 4; i++)
        ob[(size_t)(p0 + ty + i * 8) * CIN + c0 + tx] = tile[tx][ty + i * 8];
}

// ---------------- kernel: transpose reg_w to [k][oc] -----------------------
__global__ void k_wt(const float* __restrict__ reg_w) {
    int idx = blockIdx.x * 256 + threadIdx.x;
    if (idx >= KTOT * COUT) return;
    int oc  = idx & 255;
    int k   = idx >> 8;
    int tap = k >> 8;
    int c   = k & 255;
    g_wT[idx] = reg_w[(size_t)(oc * CIN + c) * KKT + tap];
}

// ---------------- kernel: fuse offset_w + mod_w into [tap][oc][c] ----------
__global__ void k_wom(const float* __restrict__ ow, const float* __restrict__ mw) {
    int idx = blockIdx.x * 256 + threadIdx.x;
    if (idx >= KKT * 27 * CIN) return;
    int c   = idx & 255;
    int r   = idx >> 8;
    int oc  = r % 27;
    int tap = r / 27;
    float v = (oc < 18) ? ow[(size_t)(oc * CIN + c) * KKT + tap]
                        : mw[(size_t)((oc - 18) * CIN + c) * KKT + tap];
    g_wom[idx] = v;
}

// ---------------- kernel: offset/mod conv + sampling prep (channel-major) --
// 1024 blocks = 32-px chunks. 256 thr: warp = 4 px x 8 c-lanes.
// Each thread accumulates 27 outputs over its strided 32-channel subset,
// x loads are warp-contiguous 512B (4 wf). Weights staged per-tap in smem.
__global__ void __launch_bounds__(256) k_offmod(const float* __restrict__ off_b,
                                                const float* __restrict__ mod_b) {
    __shared__ __align__(16) float sw[27 * CIN];   // 27 KB
    __shared__ float red[32][28];
    int blk  = blockIdx.x;
    int b    = blk >> 7;
    int pos0 = (blk & 127) << 5;                   // 32-px chunk (same row)
    int tid  = threadIdx.x;
    int l    = tid & 31;
    int wrp  = tid >> 5;
    int pxi  = wrp * 4 + (l >> 3);                 // 0..31
    int cl   = l & 7;                              // channel lane
    int pos  = pos0 + pxi;
    int y    = pos >> 6;
    int xc   = pos & 63;

    ull acc[27];
#pragma unroll
    for (int oc = 0; oc < 27; oc++) acc[oc] = 0ULL;

    const float4* X4 = (const float4*)g_xn;

    for (int tap = 0; tap < 9; tap++) {
        __syncthreads();
        {
            const float4* ws = (const float4*)(g_wom + tap * 27 * CIN);
            float4* wd = (float4*)sw;
            for (int i = tid; i < 27 * 64; i += 256) wd[i] = ws[i];
        }
        __syncthreads();
        int y2 = y + tap / 3 - 1;
        int x2 = xc + tap % 3 - 1;
        bool valid = (y2 >= 0) && (y2 < HH) && (x2 >= 0) && (x2 < WW);
        const float4* xp = X4 + (size_t)(b * HWSZ + y2 * WW + x2) * 64;
#pragma unroll
        for (int i = 0; i < 8; i++) {
            int c4 = cl + i * 8;
            float4 xv = valid ? xp[c4] : make_float4(0.f, 0.f, 0.f, 0.f);
            ulonglong2 ux = *(ulonglong2*)&xv;
#pragma unroll
            for (int oc = 0; oc < 27; oc++) {
                ulonglong2 uw = *(const ulonglong2*)&sw[oc * CIN + c4 * 4];
                acc[oc] = fma2(ux.x, uw.x, acc[oc]);
                acc[oc] = fma2(ux.y, uw.y, acc[oc]);
            }
        }
    }

    // reduce over the 8 channel-lanes
#pragma unroll
    for (int oc = 0; oc < 27; oc++) {
        float v = sum2(acc[oc]);
        v += __shfl_xor_sync(0xffffffffu, v, 4);
        v += __shfl_xor_sync(0xffffffffu, v, 2);
        v += __shfl_xor_sync(0xffffffffu, v, 1);
        if (cl == 0) red[pxi][oc] = v;
    }
    __syncthreads();

    // prep: 288 (px, tap) work items
    for (int w = tid; w < 32 * 9; w += 256) {
        int px  = w / 9;
        int tap = w - px * 9;
        int p2  = pos0 + px;
        int yy  = p2 >> 6;
        int xx  = p2 & 63;
        float ay = red[px][2 * tap]     + off_b[2 * tap];
        float ax = red[px][2 * tap + 1] + off_b[2 * tap + 1];
        float am = red[px][18 + tap]    + mod_b[tap];
        float dyo = fminf(fmaxf(ay, -16.f), 16.f);
        float dxo = fminf(fmaxf(ax, -16.f), 16.f);
        float m   = 1.f / (1.f + __expf(-am));
        float py  = dyo + (float)(tap / 3) + (float)yy - 1.f;
        float px_ = dxo + (float)(tap % 3) + (float)xx - 1.f;
        float y0f = floorf(py), x0f = floorf(px_);
        float ly  = py - y0f,   lx  = px_ - x0f;
        int y0 = (int)y0f, x0 = (int)x0f;
        bool vy0 = (y0 >= 0)     && (y0 < HH);
        bool vy1 = (y0 + 1 >= 0) && (y0 + 1 < HH);
        bool vx0 = (x0 >= 0)     && (x0 < WW);
        bool vx1 = (x0 + 1 >= 0) && (x0 + 1 < WW);
        float w00 = (1.f - ly) * (1.f - lx) * m * ((vy0 && vx0) ? 1.f : 0.f);
        float w01 = (1.f - ly) * lx         * m * ((vy0 && vx1) ? 1.f : 0.f);
        float w10 = ly * (1.f - lx)         * m * ((vy1 && vx0) ? 1.f : 0.f);
        float w11 = ly * lx                 * m * ((vy1 && vx1) ? 1.f : 0.f);
        int y0c = min(max(y0, 0), HH - 1);
        int y1c = min(max(y0 + 1, 0), HH - 1);
        int x0c = min(max(x0, 0), WW - 1);
        int x1c = min(max(x0 + 1, 0), WW - 1);
        int si = (b * 9 + tap) * HWSZ + p2;
        g_sxy[si] = make_short4((short)y0c, (short)y1c, (short)x0c, (short)x1c);
        g_swt[si] = make_float4(w00, w01, w10, w11);
    }
}

// ---------------- kernel: bilinear gather -> tiled im2col g_A --------------
__global__ void __launch_bounds__(256) k_gather() {
    __shared__ float sA[256 * 33];
    int blk = blockIdx.x;
    int bt  = blk >> 7;                     // b*9+tap
    int p32 = blk & 127;
    int b   = bt / 9;
    int pos0 = p32 << 5;
    int tid = threadIdx.x;
    int px  = tid >> 3;
    int cs  = tid & 7;

    int si = bt * HWSZ + pos0 + px;
    short4 s  = g_sxy[si];
    float4 wc = g_swt[si];
    int pb  = b * HWSZ;
    int a00 = (pb + s.x * WW + s.z) << 6;
    int a01 = (pb + s.x * WW + s.w) << 6;
    int a10 = (pb + s.y * WW + s.z) << 6;
    int a11 = (pb + s.y * WW + s.w) << 6;
    const float4* X4 = (const float4*)g_xn;

#pragma unroll
    for (int i = 0; i < 8; i++) {
        int c4 = i * 8 + cs;
        float4 v0 = X4[a00 + c4];
        float4 v1 = X4[a01 + c4];
        float4 v2 = X4[a10 + c4];
        float4 v3 = X4[a11 + c4];
        int c = c4 * 4;
        sA[(c + 0) * 33 + px] = wc.x * v0.x + wc.y * v1.x + wc.z * v2.x + wc.w * v3.x;
        sA[(c + 1) * 33 + px] = wc.x * v0.y + wc.y * v1.y + wc.z * v2.y + wc.w * v3.y;
        sA[(c + 2) * 33 + px] = wc.x * v0.z + wc.y * v1.z + wc.z * v2.z + wc.w * v3.z;
        sA[(c + 3) * 33 + px] = wc.x * v0.w + wc.y * v1.w + wc.z * v2.w + wc.w * v3.w;
    }
    __syncthreads();

    size_t obase = ((size_t)bt * 32 + (p32 >> 2)) * 16 * 2048;
    int mo  = (p32 & 3) << 5;
    int r8  = tid >> 5;
    int pxw = tid & 31;
#pragma unroll 8
    for (int pass = 0; pass < 32; pass++) {
        int c = pass * 8 + r8;
        g_A[obase + (size_t)(c >> 4) * 2048 + (c & 15) * 128 + mo + pxw] = sA[c * 33 + pxw];
    }
}

// ---------------- kernel: main GEMM (cp.async, K-stage 32, double buffer) --
__global__ void __launch_bounds__(256, 2) k_main(float* __restrict__ out) {
    __shared__ __align__(16) float As[2][32 * 128];   // 32 KB
    __shared__ __align__(16) float Bs[2][32 * 128];   // 32 KB

    int mb   = blockIdx.x;           // b*32 + mchunk
    int b    = mb >> 5;
    int mch  = mb & 31;
    int pos0 = mch << 7;
    int noff = blockIdx.y << 7;

    int tid = threadIdx.x;
    int tx  = tid & 15;
    int ty  = tid >> 4;

    unsigned int sa0 = (unsigned int)__cvta_generic_to_shared(&As[0][0]);
    unsigned int sa1 = (unsigned int)__cvta_generic_to_shared(&As[1][0]);
    unsigned int sb0 = (unsigned int)__cvta_generic_to_shared(&Bs[0][0]);
    unsigned int sb1 = (unsigned int)__cvta_generic_to_shared(&Bs[1][0]);

    size_t Ab0 = ((size_t)b * 9 * 32 + mch) * 32768;   // float index
    int krB = tid >> 3, cBB = tid & 7;                 // B fill: 32 rows x 8 groups

    ull acc[4][8];
#pragma unroll
    for (int i = 0; i < 4; i++)
#pragma unroll
        for (int j = 0; j < 8; j++) acc[i][j] = 0ULL;

#define ISSUE(s, sa, sb)                                                            \
    {                                                                               \
        const float* ap = g_A + Ab0 + (size_t)((s) >> 3) * 1048576 + ((s) & 7) * 4096; \
        cpa16((sa) + (tid) * 16,          ap + (size_t)tid * 4);                    \
        cpa16((sa) + (tid + 256) * 16,    ap + (size_t)(tid + 256) * 4);            \
        cpa16((sa) + (tid + 512) * 16,    ap + (size_t)(tid + 512) * 4);            \
        cpa16((sa) + (tid + 768) * 16,    ap + (size_t)(tid + 768) * 4);            \
        const float* bp = g_wT + ((size_t)(s) * 32 + krB) * 256 + noff + cBB * 16;  \
        cpa16((sb) + (krB * 128 + cBB * 16) * 4,      bp);                          \
        cpa16((sb) + (krB * 128 + cBB * 16 + 4) * 4,  bp + 4);                      \
        cpa16((sb) + (krB * 128 + cBB * 16 + 8) * 4,  bp + 8);                      \
        cpa16((sb) + (krB * 128 + cBB * 16 + 12) * 4, bp + 12);                     \
    }

    ISSUE(0, sa0, sb0);
    asm volatile("cp.async.commit_group;" ::: "memory");

    for (int s = 0; s < 72; s++) {
        if (s < 71) {
            if ((s + 1) & 1) { ISSUE(s + 1, sa1, sb1); }
            else             { ISSUE(s + 1, sa0, sb0); }
        }
        asm volatile("cp.async.commit_group;" ::: "memory");
        asm volatile("cp.async.wait_group 1;" ::: "memory");
        __syncthreads();

        const float* Ab = (s & 1) ? &As[1][0] : &As[0][0];
        const float* Bb = (s & 1) ? &Bs[1][0] : &Bs[0][0];
#pragma unroll 16
        for (int kk = 0; kk < 32; kk++) {
            const ulonglong2* A2 = (const ulonglong2*)(Ab + kk * 128 + ty * 8);
            ulonglong2 ua0 = A2[0];
            ulonglong2 ua1 = A2[1];
            ull ap[4] = {ua0.x, ua0.y, ua1.x, ua1.y};
            float4 b0 = *(const float4*)(Bb + kk * 128 + tx * 4);
            float4 b1 = *(const float4*)(Bb + kk * 128 + 64 + tx * 4);
            ull bd[8] = {dup2(b0.x), dup2(b0.y), dup2(b0.z), dup2(b0.w),
                         dup2(b1.x), dup2(b1.y), dup2(b1.z), dup2(b1.w)};
#pragma unroll
            for (int i = 0; i < 4; i++)
#pragma unroll
                for (int j = 0; j < 8; j++)
                    acc[i][j] = fma2(ap[i], bd[j], acc[i][j]);
        }
        __syncthreads();
    }
#undef ISSUE

    // ---- epilogue: float2 stores (pairs along M)
    int mbase = pos0 + (ty << 3);
#pragma unroll
    for (int j = 0; j < 8; j++) {
        int oc = noff + ((j < 4) ? (4 * tx + j) : (64 + 4 * tx + (j - 4)));
        float* ob = out + (size_t)(b * COUT + oc) * HWSZ + mbase;
#pragma unroll
        for (int i2 = 0; i2 < 4; i2++) {
            float2 v = upk2(acc[i2][j]);
            *(float2*)(ob + i2 * 2) = v;
        }
    }
}

// ---------------- launch ----------------------------------------------------
extern "C" void kernel_launch(void* const* d_in, const int* in_sizes, int n_in,
                              void* d_out, int out_size) {
    const float* x        = (const float*)d_in[0];
    const float* offset_w = (const float*)d_in[1];
    const float* offset_b = (const float*)d_in[2];
    const float* mod_w    = (const float*)d_in[3];
    const float* mod_b    = (const float*)d_in[4];
    const float* reg_w    = (const float*)d_in[5];
    float* out = (float*)d_out;

    k_transpose<<<dim3(128, 8, 8), dim3(32, 8)>>>(x);
    k_wt<<<(KTOT * COUT + 255) / 256, 256>>>(reg_w);
    k_wom<<<(KKT * 27 * CIN + 255) / 256, 256>>>(offset_w, mod_w);
    k_offmod<<<1024, 256>>>(offset_b, mod_b);
    k_gather<<<72 * 128, 256>>>();
    k_main<<<dim3(256, 2), 256>>>(out);
}

// round 7
// speedup vs baseline: 1.1560x; 1.1560x over previous
#include <cuda_runtime.h>
#include <cuda_bf16.h>

// Problem constants
#define HH 64
#define WW 64
#define CIN 256
#define COUT 256
#define BB 8
#define KKT 9
#define HWSZ 4096            // H*W
#define KTOT 2304            // 9*256

typedef unsigned long long ull;

// ---------------- scratch (device globals: no allocation allowed) ----------
__device__ float  g_xn[BB * HWSZ * CIN];     // x in NHWC (33.5 MB)
__device__ float  g_wT[KTOT * COUT];         // W^T [k][oc], k=tap*256+c
__device__ float  g_wB[KTOT * 32];           // offset/mod weights [k][32] (27 used)
__device__ short4 g_sxy[BB * KKT * HWSZ];    // clamped corner coords
__device__ float4 g_swt[BB * KKT * HWSZ];    // bilinear*mask*valid weights
// im2col A, tiled: [(bt*32+mchunk)*16+cc][16 k][128 m]  (302 MB)
__device__ float  g_A[(size_t)BB * KKT * CIN * HWSZ];

// ---------------- helpers ---------------------------------------------------
__device__ __forceinline__ ull fma2(ull a, ull b, ull c) {
    ull d;
    asm("fma.rn.f32x2 %0, %1, %2, %3;" : "=l"(d) : "l"(a), "l"(b), "l"(c));
    return d;
}
__device__ __forceinline__ float2 upk2(ull v) {
    float2 r;
    asm("mov.b64 {%0, %1}, %2;" : "=f"(r.x), "=f"(r.y) : "l"(v));
    return r;
}
__device__ __forceinline__ ull dup2(float v) {
    ull r;
    asm("mov.b64 %0, {%1, %1};" : "=l"(r) : "f"(v));
    return r;
}
__device__ __forceinline__ void cpa16(unsigned int s, const void* g) {
    asm volatile("cp.async.cg.shared.global [%0], [%1], 16;" :: "r"(s), "l"(g));
}

// ---------------- kernel: NCHW -> NHWC transpose of x ----------------------
__global__ void k_transpose(const float* __restrict__ x) {
    __shared__ float tile[32][33];
    int b  = blockIdx.z;
    int p0 = blockIdx.x * 32;
    int c0 = blockIdx.y * 32;
    const float* xb = x    + (size_t)b * (CIN * HWSZ);
    float*       ob = g_xn + (size_t)b * (HWSZ * CIN);
    int tx = threadIdx.x, ty = threadIdx.y;
#pragma unroll
    for (int i = 0; i < 4; i++)
        tile[ty + i * 8][tx] = xb[(size_t)(c0 + ty + i * 8) * HWSZ + p0 + tx];
    __syncthreads();
#pragma unroll
    for (int i = 0; i < 4; i++)
        ob[(size_t)(p0 + ty + i * 8) * CIN + c0 + tx] = tile[tx][ty + i * 8];
}

// ---------------- kernel: transpose reg_w to [k][oc] -----------------------
__global__ void k_wt(const float* __restrict__ reg_w) {
    int idx = blockIdx.x * 256 + threadIdx.x;
    if (idx >= KTOT * COUT) return;
    int oc  = idx & 255;
    int k   = idx >> 8;
    int tap = k >> 8;
    int c   = k & 255;
    g_wT[idx] = reg_w[(size_t)(oc * CIN + c) * KKT + tap];
}

// ---------------- kernel: build g_wB [k][32] (pad to 32, zeros beyond 27) --
__global__ void k_wom(const float* __restrict__ ow, const float* __restrict__ mw) {
    int idx = blockIdx.x * 256 + threadIdx.x;
    if (idx >= KTOT * 32) return;
    int n   = idx & 31;
    int k   = idx >> 5;
    int tap = k >> 8;
    int c   = k & 255;
    float v = 0.f;
    if (n < 18)      v = ow[(size_t)(n * CIN + c) * KKT + tap];
    else if (n < 27) v = mw[(size_t)((n - 18) * CIN + c) * KKT + tap];
    g_wB[idx] = v;
}

// ---------------- kernel: offset/mod conv as register-blocked GEMM ---------
// grid 512 = (b, row). Tile M=64 (one image row), N=32, K=2304 (144 stages x16).
// 128 threads: ty=tid>>3 (16, x4 m), tx=tid&7 (8, x4 n). f32x2 accs along m.
// A staged LDG->regs->swizzled STS; next-stage LDG issued before compute.
__global__ void __launch_bounds__(128) k_offmod(const float* __restrict__ off_b,
                                                const float* __restrict__ mod_b) {
    __shared__ __align__(16) float As[16 * 64];   // [k][m], XOR-swizzled cols
    __shared__ __align__(16) float Bs[16 * 32];   // [k][n]
    __shared__ float red[64][28];

    int blk  = blockIdx.x;
    int b    = blk >> 6;
    int y    = blk & 63;            // row = m-chunk
    int pos0 = y << 6;
    int tid  = threadIdx.x;
    int tx   = tid & 7;
    int ty   = tid >> 3;
    int cs   = tid & 3;             // c4 subgroup 0..3
    int pg   = tid >> 2;            // pixel 0..31 (and +32)
    int swzS = cs << 3;             // STS column swizzle

    const float4* X4 = (const float4*)g_xn;

    ull acc[2][4];
#pragma unroll
    for (int i = 0; i < 2; i++)
#pragma unroll
        for (int j = 0; j < 4; j++) acc[i][j] = 0ULL;

    float4 ra[2], rb;

#define LOADSTAGE(s)                                                             \
    {                                                                            \
        int tap = (s) >> 4, cc = (s) & 15;                                       \
        int dy = tap / 3 - 1, dx = tap % 3 - 1;                                  \
        int y2 = y + dy;                                                         \
        bool rowok = (y2 >= 0) && (y2 < HH);                                     \
        _Pragma("unroll")                                                        \
        for (int it = 0; it < 2; it++) {                                         \
            int m = pg + it * 32;                                                \
            int x2 = m + dx;                                                     \
            bool valid = rowok && (x2 >= 0) && (x2 < WW);                        \
            const float4* p = X4 + (size_t)(b * HWSZ + y2 * WW + x2) * 64        \
                                  + cc * 4 + cs;                                 \
            ra[it] = valid ? *p : make_float4(0.f, 0.f, 0.f, 0.f);               \
        }                                                                        \
        rb = *(const float4*)(g_wB + ((size_t)(s) * 16 + (tid >> 3)) * 32        \
                              + (tid & 7) * 4);                                  \
    }

    LOADSTAGE(0);

    for (int s = 0; s < 144; s++) {
        __syncthreads();
        // STS staged regs
#pragma unroll
        for (int it = 0; it < 2; it++) {
            int m = pg + it * 32;
            int col = m ^ swzS;
            As[(cs * 4 + 0) * 64 + col] = ra[it].x;
            As[(cs * 4 + 1) * 64 + col] = ra[it].y;
            As[(cs * 4 + 2) * 64 + col] = ra[it].z;
            As[(cs * 4 + 3) * 64 + col] = ra[it].w;
        }
        *(float4*)(Bs + (tid >> 3) * 32 + (tid & 7) * 4) = rb;
        __syncthreads();
        if (s + 1 < 144) { LOADSTAGE(s + 1); }   // LDG in flight under compute
#pragma unroll
        for (int kk = 0; kk < 16; kk++) {
            ulonglong2 a2 = *(const ulonglong2*)&As[kk * 64 + ((ty * 4) ^ ((kk & 12) << 1))];
            float4 bv = *(const float4*)&Bs[kk * 32 + tx * 4];
            ull bd[4] = {dup2(bv.x), dup2(bv.y), dup2(bv.z), dup2(bv.w)};
#pragma unroll
            for (int j = 0; j < 4; j++) {
                acc[0][j] = fma2(a2.x, bd[j], acc[0][j]);
                acc[1][j] = fma2(a2.y, bd[j], acc[1][j]);
            }
        }
    }
#undef LOADSTAGE

    // transpose accs -> red[px][n]
    __syncthreads();
#pragma unroll
    for (int i = 0; i < 2; i++)
#pragma unroll
        for (int j = 0; j < 4; j++) {
            int n = tx * 4 + j;
            if (n < 27) {
                float2 v = upk2(acc[i][j]);
                red[ty * 4 + 2 * i][n]     = v.x;
                red[ty * 4 + 2 * i + 1][n] = v.y;
            }
        }
    __syncthreads();

    // prep: 576 (px, tap) items
    for (int w = tid; w < 64 * 9; w += 128) {
        int px  = w / 9;
        int tap = w - px * 9;
        int p2  = pos0 + px;
        float ay = red[px][2 * tap]     + off_b[2 * tap];
        float ax = red[px][2 * tap + 1] + off_b[2 * tap + 1];
        float am = red[px][18 + tap]    + mod_b[tap];
        float dyo = fminf(fmaxf(ay, -16.f), 16.f);
        float dxo = fminf(fmaxf(ax, -16.f), 16.f);
        float m   = 1.f / (1.f + __expf(-am));
        float py  = dyo + (float)(tap / 3) + (float)y  - 1.f;
        float px_ = dxo + (float)(tap % 3) + (float)px - 1.f;
        float y0f = floorf(py), x0f = floorf(px_);
        float ly  = py - y0f,   lx  = px_ - x0f;
        int y0 = (int)y0f, x0 = (int)x0f;
        bool vy0 = (y0 >= 0)     && (y0 < HH);
        bool vy1 = (y0 + 1 >= 0) && (y0 + 1 < HH);
        bool vx0 = (x0 >= 0)     && (x0 < WW);
        bool vx1 = (x0 + 1 >= 0) && (x0 + 1 < WW);
        float w00 = (1.f - ly) * (1.f - lx) * m * ((vy0 && vx0) ? 1.f : 0.f);
        float w01 = (1.f - ly) * lx         * m * ((vy0 && vx1) ? 1.f : 0.f);
        float w10 = ly * (1.f - lx)         * m * ((vy1 && vx0) ? 1.f : 0.f);
        float w11 = ly * lx                 * m * ((vy1 && vx1) ? 1.f : 0.f);
        int y0c = min(max(y0, 0), HH - 1);
        int y1c = min(max(y0 + 1, 0), HH - 1);
        int x0c = min(max(x0, 0), WW - 1);
        int x1c = min(max(x0 + 1, 0), WW - 1);
        int si = (b * 9 + tap) * HWSZ + p2;
        g_sxy[si] = make_short4((short)y0c, (short)y1c, (short)x0c, (short)x1c);
        g_swt[si] = make_float4(w00, w01, w10, w11);
    }
}

// ---------------- kernel: bilinear gather -> tiled im2col g_A --------------
__global__ void __launch_bounds__(256) k_gather() {
    __shared__ float sA[256 * 33];
    int blk = blockIdx.x;
    int bt  = blk >> 7;                     // b*9+tap
    int p32 = blk & 127;
    int b   = bt / 9;
    int pos0 = p32 << 5;
    int tid = threadIdx.x;
    int px  = tid >> 3;
    int cs  = tid & 7;

    int si = bt * HWSZ + pos0 + px;
    short4 s  = g_sxy[si];
    float4 wc = g_swt[si];
    int pb  = b * HWSZ;
    int a00 = (pb + s.x * WW + s.z) << 6;
    int a01 = (pb + s.x * WW + s.w) << 6;
    int a10 = (pb + s.y * WW + s.z) << 6;
    int a11 = (pb + s.y * WW + s.w) << 6;
    const float4* X4 = (const float4*)g_xn;

#pragma unroll
    for (int i = 0; i < 8; i++) {
        int c4 = i * 8 + cs;
        float4 v0 = X4[a00 + c4];
        float4 v1 = X4[a01 + c4];
        float4 v2 = X4[a10 + c4];
        float4 v3 = X4[a11 + c4];
        int c = c4 * 4;
        sA[(c + 0) * 33 + px] = wc.x * v0.x + wc.y * v1.x + wc.z * v2.x + wc.w * v3.x;
        sA[(c + 1) * 33 + px] = wc.x * v0.y + wc.y * v1.y + wc.z * v2.y + wc.w * v3.y;
        sA[(c + 2) * 33 + px] = wc.x * v0.z + wc.y * v1.z + wc.z * v2.z + wc.w * v3.z;
        sA[(c + 3) * 33 + px] = wc.x * v0.w + wc.y * v1.w + wc.z * v2.w + wc.w * v3.w;
    }
    __syncthreads();

    size_t obase = ((size_t)bt * 32 + (p32 >> 2)) * 16 * 2048;
    int mo  = (p32 & 3) << 5;
    int r8  = tid >> 5;
    int pxw = tid & 31;
#pragma unroll 8
    for (int pass = 0; pass < 32; pass++) {
        int c = pass * 8 + r8;
        g_A[obase + (size_t)(c >> 4) * 2048 + (c & 15) * 128 + mo + pxw] = sA[c * 33 + pxw];
    }
}

// ---------------- kernel: main GEMM (cp.async, K-stage 32, double buffer) --
__global__ void __launch_bounds__(256, 2) k_main(float* __restrict__ out) {
    __shared__ __align__(16) float As[2][32 * 128];   // 32 KB
    __shared__ __align__(16) float Bs[2][32 * 128];   // 32 KB

    int mb   = blockIdx.x;           // b*32 + mchunk
    int b    = mb >> 5;
    int mch  = mb & 31;
    int pos0 = mch << 7;
    int noff = blockIdx.y << 7;

    int tid = threadIdx.x;
    int tx  = tid & 15;
    int ty  = tid >> 4;

    unsigned int sa0 = (unsigned int)__cvta_generic_to_shared(&As[0][0]);
    unsigned int sa1 = (unsigned int)__cvta_generic_to_shared(&As[1][0]);
    unsigned int sb0 = (unsigned int)__cvta_generic_to_shared(&Bs[0][0]);
    unsigned int sb1 = (unsigned int)__cvta_generic_to_shared(&Bs[1][0]);

    size_t Ab0 = ((size_t)b * 9 * 32 + mch) * 32768;   // float index
    int krB = tid >> 3, cBB = tid & 7;                 // B fill: 32 rows x 8 groups

    ull acc[4][8];
#pragma unroll
    for (int i = 0; i < 4; i++)
#pragma unroll
        for (int j = 0; j < 8; j++) acc[i][j] = 0ULL;

#define ISSUE(s, sa, sb)                                                            \
    {                                                                               \
        const float* ap = g_A + Ab0 + (size_t)((s) >> 3) * 1048576 + ((s) & 7) * 4096; \
        cpa16((sa) + (tid) * 16,          ap + (size_t)tid * 4);                    \
        cpa16((sa) + (tid + 256) * 16,    ap + (size_t)(tid + 256) * 4);            \
        cpa16((sa) + (tid + 512) * 16,    ap + (size_t)(tid + 512) * 4);            \
        cpa16((sa) + (tid + 768) * 16,    ap + (size_t)(tid + 768) * 4);            \
        const float* bp = g_wT + ((size_t)(s) * 32 + krB) * 256 + noff + cBB * 16;  \
        cpa16((sb) + (krB * 128 + cBB * 16) * 4,      bp);                          \
        cpa16((sb) + (krB * 128 + cBB * 16 + 4) * 4,  bp + 4);                      \
        cpa16((sb) + (krB * 128 + cBB * 16 + 8) * 4,  bp + 8);                      \
        cpa16((sb) + (krB * 128 + cBB * 16 + 12) * 4, bp + 12);                     \
    }

    ISSUE(0, sa0, sb0);
    asm volatile("cp.async.commit_group;" ::: "memory");

    for (int s = 0; s < 72; s++) {
        if (s < 71) {
            if ((s + 1) & 1) { ISSUE(s + 1, sa1, sb1); }
            else             { ISSUE(s + 1, sa0, sb0); }
        }
        asm volatile("cp.async.commit_group;" ::: "memory");
        asm volatile("cp.async.wait_group 1;" ::: "memory");
        __syncthreads();

        const float* Ab = (s & 1) ? &As[1][0] : &As[0][0];
        const float* Bb = (s & 1) ? &Bs[1][0] : &Bs[0][0];
#pragma unroll 16
        for (int kk = 0; kk < 32; kk++) {
            const ulonglong2* A2 = (const ulonglong2*)(Ab + kk * 128 + ty * 8);
            ulonglong2 ua0 = A2[0];
            ulonglong2 ua1 = A2[1];
            ull ap[4] = {ua0.x, ua0.y, ua1.x, ua1.y};
            float4 b0 = *(const float4*)(Bb + kk * 128 + tx * 4);
            float4 b1 = *(const float4*)(Bb + kk * 128 + 64 + tx * 4);
            ull bd[8] = {dup2(b0.x), dup2(b0.y), dup2(b0.z), dup2(b0.w),
                         dup2(b1.x), dup2(b1.y), dup2(b1.z), dup2(b1.w)};
#pragma unroll
            for (int i = 0; i < 4; i++)
#pragma unroll
                for (int j = 0; j < 8; j++)
                    acc[i][j] = fma2(ap[i], bd[j], acc[i][j]);
        }
        __syncthreads();
    }
#undef ISSUE

    // ---- epilogue: float2 stores (pairs along M)
    int mbase = pos0 + (ty << 3);
#pragma unroll
    for (int j = 0; j < 8; j++) {
        int oc = noff + ((j < 4) ? (4 * tx + j) : (64 + 4 * tx + (j - 4)));
        float* ob = out + (size_t)(b * COUT + oc) * HWSZ + mbase;
#pragma unroll
        for (int i2 = 0; i2 < 4; i2++) {
            float2 v = upk2(acc[i2][j]);
            *(float2*)(ob + i2 * 2) = v;
        }
    }
}

// ---------------- launch ----------------------------------------------------
extern "C" void kernel_launch(void* const* d_in, const int* in_sizes, int n_in,
                              void* d_out, int out_size) {
    const float* x        = (const float*)d_in[0];
    const float* offset_w = (const float*)d_in[1];
    const float* offset_b = (const float*)d_in[2];
    const float* mod_w    = (const float*)d_in[3];
    const float* mod_b    = (const float*)d_in[4];
    const float* reg_w    = (const float*)d_in[5];
    float* out = (float*)d_out;

    k_transpose<<<dim3(128, 8, 8), dim3(32, 8)>>>(x);
    k_wt<<<(KTOT * COUT + 255) / 256, 256>>>(reg_w);
    k_wom<<<(KTOT * 32 + 255) / 256, 256>>>(offset_w, mod_w);
    k_offmod<<<512, 128>>>(offset_b, mod_b);
    k_gather<<<72 * 128, 256>>>();
    k_main<<<dim3(256, 2), 256>>>(out);
}

// round 8
// speedup vs baseline: 1.1560x; 1.0000x over previous
#include <cuda_runtime.h>
#include <cuda_bf16.h>

// Problem constants
#define HH 64
#define WW 64
#define CIN 256
#define COUT 256
#define BB 8
#define KKT 9
#define HWSZ 4096            // H*W
#define KTOT 2304            // 9*256

typedef unsigned long long ull;

// ---------------- scratch (device globals: no allocation allowed) ----------
__device__ float  g_xn[BB * HWSZ * CIN];     // x in NHWC (33.5 MB)
__device__ float  g_wT[KTOT * COUT];         // W^T [k][oc], k=tap*256+c
__device__ float  g_wB[KTOT * 32];           // offset/mod weights [k][32] (27 used)
__device__ short4 g_sxy[BB * KKT * HWSZ];    // clamped corner coords
__device__ float4 g_swt[BB * KKT * HWSZ];    // bilinear*mask*valid weights
// im2col A, tiled: [(bt*32+mchunk)*16+cc][16 k][128 m]  (302 MB)
__device__ float  g_A[(size_t)BB * KKT * CIN * HWSZ];

// ---------------- helpers ---------------------------------------------------
__device__ __forceinline__ ull fma2(ull a, ull b, ull c) {
    ull d;
    asm("fma.rn.f32x2 %0, %1, %2, %3;" : "=l"(d) : "l"(a), "l"(b), "l"(c));
    return d;
}
__device__ __forceinline__ float2 upk2(ull v) {
    float2 r;
    asm("mov.b64 {%0, %1}, %2;" : "=f"(r.x), "=f"(r.y) : "l"(v));
    return r;
}
__device__ __forceinline__ ull dup2(float v) {
    ull r;
    asm("mov.b64 %0, {%1, %1};" : "=l"(r) : "f"(v));
    return r;
}
__device__ __forceinline__ void cpa16(unsigned int s, const void* g) {
    asm volatile("cp.async.cg.shared.global [%0], [%1], 16;" :: "r"(s), "l"(g));
}

// ---------------- kernel: NCHW -> NHWC transpose of x ----------------------
__global__ void k_transpose(const float* __restrict__ x) {
    __shared__ float tile[32][33];
    int b  = blockIdx.z;
    int p0 = blockIdx.x * 32;
    int c0 = blockIdx.y * 32;
    const float* xb = x    + (size_t)b * (CIN * HWSZ);
    float*       ob = g_xn + (size_t)b * (HWSZ * CIN);
    int tx = threadIdx.x, ty = threadIdx.y;
#pragma unroll
    for (int i = 0; i < 4; i++)
        tile[ty + i * 8][tx] = xb[(size_t)(c0 + ty + i * 8) * HWSZ + p0 + tx];
    __syncthreads();
#pragma unroll
    for (int i = 0; i < 4; i++)
        ob[(size_t)(p0 + ty + i * 8) * CIN + c0 + tx] = tile[tx][ty + i * 8];
}

// ---------------- kernel: transpose reg_w to [k][oc] -----------------------
__global__ void k_wt(const float* __restrict__ reg_w) {
    int idx = blockIdx.x * 256 + threadIdx.x;
    if (idx >= KTOT * COUT) return;
    int oc  = idx & 255;
    int k   = idx >> 8;
    int tap = k >> 8;
    int c   = k & 255;
    g_wT[idx] = reg_w[(size_t)(oc * CIN + c) * KKT + tap];
}

// ---------------- kernel: build g_wB [k][32] (pad to 32, zeros beyond 27) --
__global__ void k_wom(const float* __restrict__ ow, const float* __restrict__ mw) {
    int idx = blockIdx.x * 256 + threadIdx.x;
    if (idx >= KTOT * 32) return;
    int n   = idx & 31;
    int k   = idx >> 5;
    int tap = k >> 8;
    int c   = k & 255;
    float v = 0.f;
    if (n < 18)      v = ow[(size_t)(n * CIN + c) * KKT + tap];
    else if (n < 27) v = mw[(size_t)((n - 18) * CIN + c) * KKT + tap];
    g_wB[idx] = v;
}

// ---------------- kernel: offset/mod conv as register-blocked GEMM ---------
// grid 512 = (b, row). Tile M=64, N=32, K=2304 as 72 stages of 32.
// 128 threads: ty=tid>>3 (16, x4 m via 2 f32x2), tx=tid&7 (8, x4 n).
// A staged LDG->regs->swizzled STS; stage s+1 LDGs issued before compute of s
// (~700-cycle prefetch distance hides L2 latency at low occupancy).
__global__ void __launch_bounds__(128) k_offmod(const float* __restrict__ off_b,
                                                const float* __restrict__ mod_b) {
    __shared__ __align__(16) float As[32 * 64];   // [k][m], XOR-swizzled cols (8 KB)
    __shared__ __align__(16) float Bs[32 * 32];   // [k][n] (4 KB)
    __shared__ float red[64][28];

    int blk  = blockIdx.x;
    int b    = blk >> 6;
    int y    = blk & 63;            // image row = M tile
    int pos0 = y << 6;
    int tid  = threadIdx.x;
    int tx   = tid & 7;
    int ty   = tid >> 3;
    int px   = tid >> 2;            // A-fill pixel 0..31 (+32)
    int cs2  = tid & 3;             // A-fill c4 subgroup
    int rB   = tid >> 3;            // B-fill row (and +16)
    int nB   = (tid & 7) * 4;

    const float4* X4 = (const float4*)g_xn;

    ull acc[2][4];
#pragma unroll
    for (int i = 0; i < 2; i++)
#pragma unroll
        for (int j = 0; j < 4; j++) acc[i][j] = 0ULL;

    float4 ra[2][2], rb[2];

#define LOADSTAGE(s)                                                             \
    {                                                                            \
        int tap = (s) >> 3, cc = (s) & 7;                                        \
        int dy = tap / 3 - 1, dx = tap % 3 - 1;                                  \
        int y2 = y + dy;                                                         \
        bool rowok = (y2 >= 0) && (y2 < HH);                                     \
        _Pragma("unroll")                                                        \
        for (int it = 0; it < 2; it++) {                                         \
            int m = px + it * 32;                                                \
            int x2 = m + dx;                                                     \
            bool valid = rowok && (x2 >= 0) && (x2 < WW);                        \
            const float4* p = X4 + (size_t)(b * HWSZ + y2 * WW + x2) * 64        \
                                  + cc * 8 + cs2;                                \
            ra[it][0] = valid ? p[0] : make_float4(0.f, 0.f, 0.f, 0.f);          \
            ra[it][1] = valid ? p[4] : make_float4(0.f, 0.f, 0.f, 0.f);          \
        }                                                                        \
        rb[0] = *(const float4*)(g_wB + ((size_t)(s) * 32 + rB) * 32 + nB);      \
        rb[1] = *(const float4*)(g_wB + ((size_t)(s) * 32 + rB + 16) * 32 + nB); \
    }

    LOADSTAGE(0);

    for (int s = 0; s < 72; s++) {
        __syncthreads();
        // STS staged regs: row kr = cs2*4 + 16h + e, col = m ^ (cs2<<3)
#pragma unroll
        for (int it = 0; it < 2; it++) {
            int col = (px + it * 32) ^ (cs2 << 3);
#pragma unroll
            for (int h = 0; h < 2; h++) {
                int kr = cs2 * 4 + h * 16;
                As[(kr + 0) * 64 + col] = (&ra[it][h].x)[0];
                As[(kr + 1) * 64 + col] = (&ra[it][h].x)[1];
                As[(kr + 2) * 64 + col] = (&ra[it][h].x)[2];
                As[(kr + 3) * 64 + col] = (&ra[it][h].x)[3];
            }
        }
        *(float4*)(Bs + rB * 32 + nB)        = rb[0];
        *(float4*)(Bs + (rB + 16) * 32 + nB) = rb[1];
        __syncthreads();
        if (s + 1 < 72) { LOADSTAGE(s + 1); }   // LDG in flight under compute
#pragma unroll
        for (int kk = 0; kk < 32; kk++) {
            ulonglong2 a2 = *(const ulonglong2*)&As[kk * 64 + ((ty * 4) ^ ((kk & 12) << 1))];
            float4 bv = *(const float4*)&Bs[kk * 32 + tx * 4];
            ull bd[4] = {dup2(bv.x), dup2(bv.y), dup2(bv.z), dup2(bv.w)};
#pragma unroll
            for (int j = 0; j < 4; j++) {
                acc[0][j] = fma2(a2.x, bd[j], acc[0][j]);
                acc[1][j] = fma2(a2.y, bd[j], acc[1][j]);
            }
        }
    }
#undef LOADSTAGE

    // transpose accs -> red[px][n]
    __syncthreads();
#pragma unroll
    for (int i = 0; i < 2; i++)
#pragma unroll
        for (int j = 0; j < 4; j++) {
            int n = tx * 4 + j;
            if (n < 27) {
                float2 v = upk2(acc[i][j]);
                red[ty * 4 + 2 * i][n]     = v.x;
                red[ty * 4 + 2 * i + 1][n] = v.y;
            }
        }
    __syncthreads();

    // prep: 576 (px, tap) items
    for (int w = tid; w < 64 * 9; w += 128) {
        int px_i = w / 9;
        int tap  = w - px_i * 9;
        int p2   = pos0 + px_i;
        float ay = red[px_i][2 * tap]     + off_b[2 * tap];
        float ax = red[px_i][2 * tap + 1] + off_b[2 * tap + 1];
        float am = red[px_i][18 + tap]    + mod_b[tap];
        float dyo = fminf(fmaxf(ay, -16.f), 16.f);
        float dxo = fminf(fmaxf(ax, -16.f), 16.f);
        float m   = 1.f / (1.f + __expf(-am));
        float py  = dyo + (float)(tap / 3) + (float)y    - 1.f;
        float px_ = dxo + (float)(tap % 3) + (float)px_i - 1.f;
        float y0f = floorf(py), x0f = floorf(px_);
        float ly  = py - y0f,   lx  = px_ - x0f;
        int y0 = (int)y0f, x0 = (int)x0f;
        bool vy0 = (y0 >= 0)     && (y0 < HH);
        bool vy1 = (y0 + 1 >= 0) && (y0 + 1 < HH);
        bool vx0 = (x0 >= 0)     && (x0 < WW);
        bool vx1 = (x0 + 1 >= 0) && (x0 + 1 < WW);
        float w00 = (1.f - ly) * (1.f - lx) * m * ((vy0 && vx0) ? 1.f : 0.f);
        float w01 = (1.f - ly) * lx         * m * ((vy0 && vx1) ? 1.f : 0.f);
        float w10 = ly * (1.f - lx)         * m * ((vy1 && vx0) ? 1.f : 0.f);
        float w11 = ly * lx                 * m * ((vy1 && vx1) ? 1.f : 0.f);
        int y0c = min(max(y0, 0), HH - 1);
        int y1c = min(max(y0 + 1, 0), HH - 1);
        int x0c = min(max(x0, 0), WW - 1);
        int x1c = min(max(x0 + 1, 0), WW - 1);
        int si = (b * 9 + tap) * HWSZ + p2;
        g_sxy[si] = make_short4((short)y0c, (short)y1c, (short)x0c, (short)x1c);
        g_swt[si] = make_float4(w00, w01, w10, w11);
    }
}

// ---------------- kernel: bilinear gather -> tiled im2col g_A --------------
// grid 1024 = (b, 32-px chunk); loops all 9 taps inside so consecutive taps'
// overlapping corner reads hit L1 (cross-tap reuse cuts L2 traffic).
__global__ void __launch_bounds__(256) k_gather() {
    __shared__ float sA[256 * 33];
    int blk = blockIdx.x;
    int b   = blk >> 7;
    int p32 = blk & 127;
    int pos0 = p32 << 5;
    int tid = threadIdx.x;
    int px  = tid >> 3;
    int cs  = tid & 7;
    int pb  = b * HWSZ;
    const float4* X4 = (const float4*)g_xn;

    int r8  = tid >> 5;
    int pxw = tid & 31;
    int mo  = (p32 & 3) << 5;

    for (int tap = 0; tap < 9; tap++) {
        int bt = b * 9 + tap;
        int si = bt * HWSZ + pos0 + px;
        short4 s  = g_sxy[si];
        float4 wc = g_swt[si];
        int a00 = (pb + s.x * WW + s.z) << 6;
        int a01 = (pb + s.x * WW + s.w) << 6;
        int a10 = (pb + s.y * WW + s.z) << 6;
        int a11 = (pb + s.y * WW + s.w) << 6;

#pragma unroll
        for (int i = 0; i < 8; i++) {
            int c4 = i * 8 + cs;
            float4 v0 = X4[a00 + c4];
            float4 v1 = X4[a01 + c4];
            float4 v2 = X4[a10 + c4];
            float4 v3 = X4[a11 + c4];
            int c = c4 * 4;
            sA[(c + 0) * 33 + px] = wc.x * v0.x + wc.y * v1.x + wc.z * v2.x + wc.w * v3.x;
            sA[(c + 1) * 33 + px] = wc.x * v0.y + wc.y * v1.y + wc.z * v2.y + wc.w * v3.y;
            sA[(c + 2) * 33 + px] = wc.x * v0.z + wc.y * v1.z + wc.z * v2.z + wc.w * v3.z;
            sA[(c + 3) * 33 + px] = wc.x * v0.w + wc.y * v1.w + wc.z * v2.w + wc.w * v3.w;
        }
        __syncthreads();

        size_t obase = ((size_t)bt * 32 + (p32 >> 2)) * 16 * 2048;
#pragma unroll 8
        for (int pass = 0; pass < 32; pass++) {
            int c = pass * 8 + r8;
            g_A[obase + (size_t)(c >> 4) * 2048 + (c & 15) * 128 + mo + pxw] = sA[c * 33 + pxw];
        }
        __syncthreads();
    }
}

// ---------------- kernel: main GEMM (cp.async, K-stage 32, double buffer) --
__global__ void __launch_bounds__(256, 2) k_main(float* __restrict__ out) {
    __shared__ __align__(16) float As[2][32 * 128];   // 32 KB
    __shared__ __align__(16) float Bs[2][32 * 128];   // 32 KB

    int mb   = blockIdx.x;           // b*32 + mchunk
    int b    = mb >> 5;
    int mch  = mb & 31;
    int pos0 = mch << 7;
    int noff = blockIdx.y << 7;

    int tid = threadIdx.x;
    int tx  = tid & 15;
    int ty  = tid >> 4;

    unsigned int sa0 = (unsigned int)__cvta_generic_to_shared(&As[0][0]);
    unsigned int sa1 = (unsigned int)__cvta_generic_to_shared(&As[1][0]);
    unsigned int sb0 = (unsigned int)__cvta_generic_to_shared(&Bs[0][0]);
    unsigned int sb1 = (unsigned int)__cvta_generic_to_shared(&Bs[1][0]);

    size_t Ab0 = ((size_t)b * 9 * 32 + mch) * 32768;   // float index
    int krB = tid >> 3, cBB = tid & 7;

    ull acc[4][8];
#pragma unroll
    for (int i = 0; i < 4; i++)
#pragma unroll
        for (int j = 0; j < 8; j++) acc[i][j] = 0ULL;

#define ISSUE(s, sa, sb)                                                            \
    {                                                                               \
        const float* ap = g_A + Ab0 + (size_t)((s) >> 3) * 1048576 + ((s) & 7) * 4096; \
        cpa16((sa) + (tid) * 16,          ap + (size_t)tid * 4);                    \
        cpa16((sa) + (tid + 256) * 16,    ap + (size_t)(tid + 256) * 4);            \
        cpa16((sa) + (tid + 512) * 16,    ap + (size_t)(tid + 512) * 4);            \
        cpa16((sa) + (tid + 768) * 16,    ap + (size_t)(tid + 768) * 4);            \
        const float* bp = g_wT + ((size_t)(s) * 32 + krB) * 256 + noff + cBB * 16;  \
        cpa16((sb) + (krB * 128 + cBB * 16) * 4,      bp);                          \
        cpa16((sb) + (krB * 128 + cBB * 16 + 4) * 4,  bp + 4);                      \
        cpa16((sb) + (krB * 128 + cBB * 16 + 8) * 4,  bp + 8);                      \
        cpa16((sb) + (krB * 128 + cBB * 16 + 12) * 4, bp + 12);                     \
    }

    ISSUE(0, sa0, sb0);
    asm volatile("cp.async.commit_group;" ::: "memory");

    for (int s = 0; s < 72; s++) {
        if (s < 71) {
            if ((s + 1) & 1) { ISSUE(s + 1, sa1, sb1); }
            else             { ISSUE(s + 1, sa0, sb0); }
        }
        asm volatile("cp.async.commit_group;" ::: "memory");
        asm volatile("cp.async.wait_group 1;" ::: "memory");
        __syncthreads();

        const float* Ab = (s & 1) ? &As[1][0] : &As[0][0];
        const float* Bb = (s & 1) ? &Bs[1][0] : &Bs[0][0];
#pragma unroll 16
        for (int kk = 0; kk < 32; kk++) {
            const ulonglong2* A2 = (const ulonglong2*)(Ab + kk * 128 + ty * 8);
            ulonglong2 ua0 = A2[0];
            ulonglong2 ua1 = A2[1];
            ull ap[4] = {ua0.x, ua0.y, ua1.x, ua1.y};
            float4 b0 = *(const float4*)(Bb + kk * 128 + tx * 4);
            float4 b1 = *(const float4*)(Bb + kk * 128 + 64 + tx * 4);
            ull bd[8] = {dup2(b0.x), dup2(b0.y), dup2(b0.z), dup2(b0.w),
                         dup2(b1.x), dup2(b1.y), dup2(b1.z), dup2(b1.w)};
#pragma unroll
            for (int i = 0; i < 4; i++)
#pragma unroll
                for (int j = 0; j < 8; j++)
                    acc[i][j] = fma2(ap[i], bd[j], acc[i][j]);
        }
        __syncthreads();
    }
#undef ISSUE

    // ---- epilogue: float2 stores (pairs along M)
    int mbase = pos0 + (ty << 3);
#pragma unroll
    for (int j = 0; j < 8; j++) {
        int oc = noff + ((j < 4) ? (4 * tx + j) : (64 + 4 * tx + (j - 4)));
        float* ob = out + (size_t)(b * COUT + oc) * HWSZ + mbase;
#pragma unroll
        for (int i2 = 0; i2 < 4; i2++) {
            float2 v = upk2(acc[i2][j]);
            *(float2*)(ob + i2 * 2) = v;
        }
    }
}

// ---------------- launch ----------------------------------------------------
extern "C" void kernel_launch(void* const* d_in, const int* in_sizes, int n_in,
                              void* d_out, int out_size) {
    const float* x        = (const float*)d_in[0];
    const float* offset_w = (const float*)d_in[1];
    const float* offset_b = (const float*)d_in[2];
    const float* mod_w    = (const float*)d_in[3];
    const float* mod_b    = (const float*)d_in[4];
    const float* reg_w    = (const float*)d_in[5];
    float* out = (float*)d_out;

    k_transpose<<<dim3(128, 8, 8), dim3(32, 8)>>>(x);
    k_wt<<<(KTOT * COUT + 255) / 256, 256>>>(reg_w);
    k_wom<<<(KTOT * 32 + 255) / 256, 256>>>(offset_w, mod_w);
    k_offmod<<<512, 128>>>(offset_b, mod_b);
    k_gather<<<1024, 256>>>();
    k_main<<<dim3(256, 2), 256>>>(out);
}